// round 15
// baseline (speedup 1.0000x reference)
#include <cuda_runtime.h>

#define BATCH 65536
#define TSTEPS 32
#define F 33
#define H 24

// Scratch for x_spatial [B, 90, 12] (row-major, contiguous per sample).
__device__ __align__(16) float g_xsp[(size_t)BATCH * 1080];
// Spike mask per (sample, timestep): bit k = spike2[k] at step t.
__device__ __align__(16) unsigned long long g_mask[(size_t)BATCH * TSTEPS];

// ---------------- f32x2 packed-FMA helpers (sm_103a FFMA2) -----------------
__device__ __forceinline__ unsigned long long pack2(float lo, float hi) {
    unsigned long long r;
    asm("mov.b64 %0, {%1, %2};" : "=l"(r) : "f"(lo), "f"(hi));
    return r;
}
__device__ __forceinline__ void fma2(unsigned long long& d, unsigned long long a,
                                     unsigned long long b) {
    asm("fma.rn.f32x2 %0, %1, %2, %0;" : "+l"(d) : "l"(a), "l"(b));
}
__device__ __forceinline__ float2 unpack2(unsigned long long v) {
    float2 f;
    asm("mov.b64 {%0, %1}, %2;" : "=f"(f.x), "=f"(f.y) : "l"(v));
    return f;
}

// ---------------------------------------------------------------------------
// Kernel A: conv1+bn1+relu -> conv2+bn2+relu -> x_spatial[b][s][c].
// One thread per (b, s); x read via 2x LDG.128 + 1 scalar; 3x STG.128 out.
// ---------------------------------------------------------------------------
__global__ __launch_bounds__(256) void conv_kernel(
    const float* __restrict__ x,
    const float* __restrict__ w1, const float* __restrict__ cb1,
    const float* __restrict__ g1, const float* __restrict__ bb1,
    const float* __restrict__ m1, const float* __restrict__ v1,
    const float* __restrict__ w2, const float* __restrict__ cb2,
    const float* __restrict__ g2, const float* __restrict__ bb2,
    const float* __restrict__ m2, const float* __restrict__ v2)
{
    __shared__ float sw1[30], sw2[216], ss1[6], sbe1[6], ss2[12], sbe2[12];
    int tx = threadIdx.x;
    if (tx < 30)  sw1[tx] = w1[tx];
    if (tx < 216) sw2[tx] = w2[tx];
    if (tx < 6) {
        float sc = g1[tx] * rsqrtf(v1[tx] + 1e-5f);
        ss1[tx]  = sc;
        sbe1[tx] = bb1[tx] + sc * (cb1[tx] - m1[tx]);
    }
    if (tx >= 32 && tx < 44) {
        int c = tx - 32;
        float sc = g2[c] * rsqrtf(v2[c] + 1e-5f);
        ss2[c]  = sc;
        sbe2[c] = bb2[c] + sc * (cb2[c] - m2[c]);
    }
    __syncthreads();

    unsigned gid = blockIdx.x * 256u + (unsigned)tx;   // 0 .. B*90-1 (exact)
    unsigned b = gid / 90u;
    int s = (int)(gid % 90u);

    const float* xb = x + (size_t)b * 360;
    float xv[9];
    if (s > 0) {
        // base = 4s-4 >= 0, 16B aligned; base+7 <= 355 < 360
        const float4* p = reinterpret_cast<const float4*>(xb + 4 * s - 4);
        float4 q0 = __ldg(p);
        float4 q1 = __ldg(p + 1);
        xv[0] = q0.x; xv[1] = q0.y; xv[2] = q0.z; xv[3] = q0.w;
        xv[4] = q1.x; xv[5] = q1.y; xv[6] = q1.z; xv[7] = q1.w;
        // idx = 4s+4: out of range (conv1 zero-pad) when s == 89
        xv[8] = (s < 89) ? __ldg(xb + 4 * s + 4) : 0.f;
    } else {
        float4 q0 = __ldg(reinterpret_cast<const float4*>(xb));
        xv[0] = 0.f; xv[1] = 0.f; xv[2] = 0.f; xv[3] = 0.f;
        xv[4] = q0.x; xv[5] = q0.y; xv[6] = q0.z; xv[7] = q0.w;
        xv[8] = __ldg(xb + 4);
    }

    float h1v[6][3];
#pragma unroll
    for (int q = 0; q < 3; q++) {
        bool valid = (2 * s - 1 + q) >= 0;
#pragma unroll
        for (int c = 0; c < 6; c++) {
            float a = 0.f;
#pragma unroll
            for (int k = 0; k < 5; k++) a = fmaf(sw1[c * 5 + k], xv[2 * q + k], a);
            a = ss1[c] * a + sbe1[c];
            h1v[c][q] = valid ? fmaxf(a, 0.f) : 0.f;
        }
    }

    float ov[12];
#pragma unroll
    for (int c2 = 0; c2 < 12; c2++) {
        float a = 0.f;
#pragma unroll
        for (int c1 = 0; c1 < 6; c1++)
#pragma unroll
            for (int q = 0; q < 3; q++)
                a = fmaf(sw2[(c2 * 6 + c1) * 3 + q], h1v[c1][q], a);
        a = ss2[c2] * a + sbe2[c2];
        ov[c2] = fmaxf(a, 0.f);
    }
    float4* o4 = reinterpret_cast<float4*>(g_xsp + (size_t)b * 1080 + s * 12);
    o4[0] = make_float4(ov[0], ov[1], ov[2],  ov[3]);
    o4[1] = make_float4(ov[4], ov[5], ov[6],  ov[7]);
    o4[2] = make_float4(ov[8], ov[9], ov[10], ov[11]);
}

// ---------------------------------------------------------------------------
// Kernel B: double LIF, 8 lanes per sample (lane owns k = lane+8i).
// Emits per-(b,t) 33-bit spike mask as uint64.
// ---------------------------------------------------------------------------
__global__ __launch_bounds__(256) void lif_kernel()
{
    unsigned gtid = blockIdx.x * 256u + threadIdx.x;   // B*8 threads
    unsigned b = gtid >> 3;
    int lane = threadIdx.x & 7;
    const float* fl = g_xsp + (size_t)b * 1080;

    float mem1[5], mem2[5];
#pragma unroll
    for (int i = 0; i < 5; i++) { mem1[i] = 0.f; mem2[i] = 0.f; }

#pragma unroll 1
    for (int t = 0; t < TSTEPS; t++) {
        const float* xt = fl + t * F;
        unsigned long long pm = 0ull;
#pragma unroll
        for (int i = 0; i < 5; i++) {
            if (i < 4 || lane == 0) {           // k = lane + 8i < 33
                int k = lane + 8 * i;
                float in = __ldg(xt + k);
                float a = 0.95f * mem1[i] + in;
                float s1 = (a > 0.5f) ? 1.f : 0.f;
                mem1[i] = a * (1.f - s1);
                float bm = 0.9f * mem2[i] + s1;
                if (bm > 0.6f) { pm |= (1ull << k); mem2[i] = 0.f; }
                else mem2[i] = bm;
            }
        }
        pm |= __shfl_xor_sync(0xffffffffu, pm, 1, 8);
        pm |= __shfl_xor_sync(0xffffffffu, pm, 2, 8);
        pm |= __shfl_xor_sync(0xffffffffu, pm, 4, 8);
        if (lane == 0) g_mask[(size_t)b * TSTEPS + t] = pm;
    }
}

// ---------------------------------------------------------------------------
// Kernel C: LSTM (FFMA2 packed gates) + head. 8 lanes x 4 samples per thread.
// Gates packed: aIF = (i,f), aGO = (g,o). One LDS.128 = 2 FFMA2 operands.
// ---------------------------------------------------------------------------
__device__ __forceinline__ float sigf(float x) {
    return __fdividef(1.f, 1.f + __expf(-x));
}
__device__ __forceinline__ float tanhfast(float x) {
    float e = __expf(2.f * x);
    return 1.f - __fdividef(2.f, e + 1.f);   // correct limits at +/-inf
}

#define NS 4   // samples per thread

__global__ __launch_bounds__(256) void lstm_head_kernel(
    const float* __restrict__ wih, const float* __restrict__ whh,
    const float* __restrict__ bih, const float* __restrict__ bhh,
    const float* __restrict__ rtw1, const float* __restrict__ rtb1,
    const float* __restrict__ rtw2, const float* __restrict__ rtb2,
    const float* __restrict__ fw,  const float* __restrict__ fb,
    const float* __restrict__ cw1, const float* __restrict__ cb1_,
    const float* __restrict__ cw2, const float* __restrict__ cb2_,
    float* __restrict__ out)
{
    __shared__ ulonglong2 sWp[F * 24];   // {(Wi,Wf),(Wg,Wo)}[k][j]
    __shared__ ulonglong2 sHp[24 * 24];
    __shared__ ulonglong2 sBs[24];
    __shared__ float s_rtw1[12 * 36], s_rtb1[12], s_rtw2[24], s_rtb2[2];
    __shared__ float s_fw[24 * 36], s_fb[24];
    __shared__ float s_cw1[12 * 24], s_cb1[12], s_cw2[60], s_cb2[5];

    int tx = threadIdx.x;
    for (int i = tx; i < F * 24; i += 256) {
        int k = i / 24, j = i % 24;
        sWp[i].x = pack2(wih[j * F + k],        wih[(24 + j) * F + k]);
        sWp[i].y = pack2(wih[(48 + j) * F + k], wih[(72 + j) * F + k]);
    }
    for (int i = tx; i < 24 * 24; i += 256) {
        int k = i / 24, j = i % 24;
        sHp[i].x = pack2(whh[j * 24 + k],        whh[(24 + j) * 24 + k]);
        sHp[i].y = pack2(whh[(48 + j) * 24 + k], whh[(72 + j) * 24 + k]);
    }
    if (tx < 24) {
        sBs[tx].x = pack2(bih[tx] + bhh[tx],           bih[24 + tx] + bhh[24 + tx]);
        sBs[tx].y = pack2(bih[48 + tx] + bhh[48 + tx], bih[72 + tx] + bhh[72 + tx]);
    }
    for (int i = tx; i < 432; i += 256) s_rtw1[i] = rtw1[i];
    if (tx < 12) s_rtb1[tx] = rtb1[tx];
    if (tx < 24) s_rtw2[tx] = rtw2[tx];
    if (tx < 2)  s_rtb2[tx] = rtb2[tx];
    for (int i = tx; i < 864; i += 256) s_fw[i] = fw[i];
    if (tx < 24) s_fb[tx] = fb[tx];
    for (int i = tx; i < 288; i += 256) s_cw1[i] = cw1[i];
    if (tx < 12) s_cb1[tx] = cb1_[tx];
    if (tx < 60) s_cw2[tx] = cw2[tx];
    if (tx < 5)  s_cb2[tx] = cb2_[tx];
    __syncthreads();

    unsigned gtid = blockIdx.x * 256u + (unsigned)tx;
    unsigned grp = gtid >> 3;          // 8 lanes per group of NS samples
    int lane = tx & 7;
    int j0 = lane * 3;
    unsigned bb = grp * NS;

    float hs[NS][3], cs[NS][3];
#pragma unroll
    for (int s = 0; s < NS; s++)
#pragma unroll
        for (int u = 0; u < 3; u++) { hs[s][u] = 0.f; cs[s][u] = 0.f; }

#pragma unroll 1
    for (int t = 0; t < TSTEPS; t++) {
        unsigned long long mk[NS];
#pragma unroll
        for (int s = 0; s < NS; s++)
            mk[s] = __ldg(&g_mask[(size_t)(bb + s) * TSTEPS + t]);

        unsigned long long aIF[NS][3], aGO[NS][3];
        {
            ulonglong2 b0 = sBs[j0], b1 = sBs[j0 + 1], b2 = sBs[j0 + 2];
#pragma unroll
            for (int s = 0; s < NS; s++) {
                aIF[s][0] = b0.x; aGO[s][0] = b0.y;
                aIF[s][1] = b1.x; aGO[s][1] = b1.y;
                aIF[s][2] = b2.x; aGO[s][2] = b2.y;
            }
        }
#pragma unroll
        for (int k = 0; k < F; k++) {
            ulonglong2 w0 = sWp[k * 24 + j0];
            ulonglong2 w1 = sWp[k * 24 + j0 + 1];
            ulonglong2 w2 = sWp[k * 24 + j0 + 2];
#pragma unroll
            for (int s = 0; s < NS; s++) {
                float f = (float)((unsigned)(mk[s] >> k) & 1u);
                unsigned long long fp = pack2(f, f);
                fma2(aIF[s][0], fp, w0.x); fma2(aGO[s][0], fp, w0.y);
                fma2(aIF[s][1], fp, w1.x); fma2(aGO[s][1], fp, w1.y);
                fma2(aIF[s][2], fp, w2.x); fma2(aGO[s][2], fp, w2.y);
            }
        }
#pragma unroll
        for (int k = 0; k < H; k++) {
            ulonglong2 w0 = sHp[k * 24 + j0];
            ulonglong2 w1 = sHp[k * 24 + j0 + 1];
            ulonglong2 w2 = sHp[k * 24 + j0 + 2];
#pragma unroll
            for (int s = 0; s < NS; s++) {
                float hk = hs[s][k % 3];
                float f = __shfl_sync(0xffffffffu, hk, k / 3, 8);
                unsigned long long fp = pack2(f, f);
                fma2(aIF[s][0], fp, w0.x); fma2(aGO[s][0], fp, w0.y);
                fma2(aIF[s][1], fp, w1.x); fma2(aGO[s][1], fp, w1.y);
                fma2(aIF[s][2], fp, w2.x); fma2(aGO[s][2], fp, w2.y);
            }
        }
#pragma unroll
        for (int s = 0; s < NS; s++) {
#pragma unroll
            for (int u = 0; u < 3; u++) {
                float2 gif = unpack2(aIF[s][u]);
                float2 ggo = unpack2(aGO[s][u]);
                float gi = sigf(gif.x);
                float gf = sigf(gif.y);
                float gg = tanhfast(ggo.x);
                float go = sigf(ggo.y);
                cs[s][u] = gf * cs[s][u] + gi * gg;
                hs[s][u] = go * tanhfast(cs[s][u]);
            }
        }
    }

    // --- head, one sample at a time (registers reused) ---
#pragma unroll 1
    for (int smp = 0; smp < NS; smp++) {
        unsigned b = bb + smp;
        const float* fl = g_xsp + (size_t)b * 1080;

        float comb[36];
#pragma unroll
        for (int k = 0; k < 24; k++) {
            float hk = hs[smp][k % 3];
            comb[k] = __shfl_sync(0xffffffffu, hk, k / 3, 8);
        }

        float pv[12];
#pragma unroll
        for (int i = 0; i < 12; i++) pv[i] = 0.f;
        const float4* x4 = reinterpret_cast<const float4*>(fl);
#pragma unroll 1
        for (int s = lane; s < 90; s += 8) {
            float4 q0 = __ldg(x4 + s * 3);
            float4 q1 = __ldg(x4 + s * 3 + 1);
            float4 q2 = __ldg(x4 + s * 3 + 2);
            pv[0] += q0.x; pv[1] += q0.y; pv[2]  += q0.z; pv[3]  += q0.w;
            pv[4] += q1.x; pv[5] += q1.y; pv[6]  += q1.z; pv[7]  += q1.w;
            pv[8] += q2.x; pv[9] += q2.y; pv[10] += q2.z; pv[11] += q2.w;
        }
#pragma unroll
        for (int i = 0; i < 12; i++) {
            float v = pv[i];
            v += __shfl_xor_sync(0xffffffffu, v, 1, 8);
            v += __shfl_xor_sync(0xffffffffu, v, 2, 8);
            v += __shfl_xor_sync(0xffffffffu, v, 4, 8);
            comb[24 + i] = v * (1.f / 90.f);
        }

        float z1[12];
#pragma unroll
        for (int i = 0; i < 12; i++) {
            float a = s_rtb1[i];
#pragma unroll
            for (int k = 0; k < 36; k++) a = fmaf(s_rtw1[i * 36 + k], comb[k], a);
            z1[i] = fmaxf(a, 0.f);
        }
        float z2[2];
#pragma unroll
        for (int i = 0; i < 2; i++) {
            float a = s_rtb2[i];
#pragma unroll
            for (int k = 0; k < 12; k++) a = fmaf(s_rtw2[i * 12 + k], z1[k], a);
            z2[i] = a;
        }
        float mx = fmaxf(z2[0], z2[1]);
        float e0 = __expf(z2[0] - mx), e1 = __expf(z2[1] - mx);
        float inv = 1.f / (e0 + e1);
        float rw0 = 0.7f * (e0 * inv), rw1 = 0.3f * (e1 * inv);
        float alpha = rw0 / (rw0 + rw1);
        float om = 1.f - alpha;

        float fin[36];
#pragma unroll
        for (int j = 0; j < 24; j++) fin[j] = comb[j] * alpha;
#pragma unroll
        for (int i = 0; i < 12; i++) fin[24 + i] = comb[24 + i] * om;

        float fused[24];
#pragma unroll
        for (int i = 0; i < 24; i++) {
            float a = s_fb[i];
#pragma unroll
            for (int k = 0; k < 36; k++) a = fmaf(s_fw[i * 36 + k], fin[k], a);
            fused[i] = fmaxf(a, 0.f);
        }
        float y1[12];
#pragma unroll
        for (int i = 0; i < 12; i++) {
            float a = s_cb1[i];
#pragma unroll
            for (int k = 0; k < 24; k++) a = fmaf(s_cw1[i * 24 + k], fused[k], a);
            y1[i] = fmaxf(a, 0.f);
        }
        if (lane == 0) {
            float* ob = out + (size_t)b * 5;
#pragma unroll
            for (int i = 0; i < 5; i++) {
                float a = s_cb2[i];
#pragma unroll
                for (int k = 0; k < 12; k++) a = fmaf(s_cw2[i * 12 + k], y1[k], a);
                ob[i] = a;
            }
        }
    }
}

extern "C" void kernel_launch(void* const* d_in, const int* in_sizes, int n_in,
                              void* d_out, int out_size) {
    const float* x   = (const float*)d_in[0];
    const float* c1w = (const float*)d_in[1];
    const float* c1b = (const float*)d_in[2];
    const float* b1g = (const float*)d_in[3];
    const float* b1b = (const float*)d_in[4];
    const float* b1m = (const float*)d_in[5];
    const float* b1v = (const float*)d_in[6];
    const float* c2w = (const float*)d_in[7];
    const float* c2b = (const float*)d_in[8];
    const float* b2g = (const float*)d_in[9];
    const float* b2b = (const float*)d_in[10];
    const float* b2m = (const float*)d_in[11];
    const float* b2v = (const float*)d_in[12];
    const float* wih = (const float*)d_in[13];
    const float* whh = (const float*)d_in[14];
    const float* bih = (const float*)d_in[15];
    const float* bhh = (const float*)d_in[16];
    const float* rtw1 = (const float*)d_in[17];
    const float* rtb1 = (const float*)d_in[18];
    const float* rtw2 = (const float*)d_in[19];
    const float* rtb2 = (const float*)d_in[20];
    const float* fw  = (const float*)d_in[21];
    const float* fb  = (const float*)d_in[22];
    const float* cw1 = (const float*)d_in[23];
    const float* cb1 = (const float*)d_in[24];
    const float* cw2 = (const float*)d_in[25];
    const float* cb2 = (const float*)d_in[26];
    float* out = (float*)d_out;

    // B*90 = 5,898,240 threads -> exactly 23040 blocks of 256
    conv_kernel<<<23040, 256>>>(x, c1w, c1b, b1g, b1b, b1m, b1v,
                                c2w, c2b, b2g, b2b, b2m, b2v);
    // B*8 threads -> 2048 blocks of 256
    lif_kernel<<<2048, 256>>>();
    // (B/4) groups * 8 lanes = 131072 threads -> 512 blocks of 256
    lstm_head_kernel<<<512, 256>>>(wih, whh, bih, bhh,
                                   rtw1, rtb1, rtw2, rtb2,
                                   fw, fb, cw1, cb1, cw2, cb2, out);
}

// round 17
// speedup vs baseline: 1.5440x; 1.5440x over previous
#include <cuda_runtime.h>

#define BATCH 65536
#define TSTEPS 32
#define F 33
#define H 24

// Scratch for x_spatial [B, 90, 12] (row-major, contiguous per sample).
__device__ __align__(16) float g_xsp[(size_t)BATCH * 1080];
// Spike mask per (sample, timestep): bit k = spike2[k] at step t.
__device__ __align__(16) unsigned long long g_mask[(size_t)BATCH * TSTEPS];

// ---------------- f32x2 packed-FMA helpers (sm_103a FFMA2) -----------------
__device__ __forceinline__ unsigned long long pack2(float lo, float hi) {
    unsigned long long r;
    asm("mov.b64 %0, {%1, %2};" : "=l"(r) : "f"(lo), "f"(hi));
    return r;
}
__device__ __forceinline__ void fma2(unsigned long long& d, unsigned long long a,
                                     unsigned long long b) {
    asm("fma.rn.f32x2 %0, %1, %2, %0;" : "+l"(d) : "l"(a), "l"(b));
}
__device__ __forceinline__ float2 unpack2(unsigned long long v) {
    float2 f;
    asm("mov.b64 {%0, %1}, %2;" : "=f"(f.x), "=f"(f.y) : "l"(v));
    return f;
}

// ---------------------------------------------------------------------------
// Kernel A: conv1+bn1+relu -> conv2+bn2+relu -> x_spatial[b][s][c].
// One thread per (b, s). EXACT R11 version (measured 162 us — clock reference).
// ---------------------------------------------------------------------------
__global__ __launch_bounds__(256) void conv_kernel(
    const float* __restrict__ x,
    const float* __restrict__ w1, const float* __restrict__ cb1,
    const float* __restrict__ g1, const float* __restrict__ bb1,
    const float* __restrict__ m1, const float* __restrict__ v1,
    const float* __restrict__ w2, const float* __restrict__ cb2,
    const float* __restrict__ g2, const float* __restrict__ bb2,
    const float* __restrict__ m2, const float* __restrict__ v2)
{
    __shared__ float sw1[30], sw2[216], ss1[6], sbe1[6], ss2[12], sbe2[12];
    int tx = threadIdx.x;
    if (tx < 30)  sw1[tx] = w1[tx];
    if (tx < 216) sw2[tx] = w2[tx];
    if (tx < 6) {
        float sc = g1[tx] * rsqrtf(v1[tx] + 1e-5f);
        ss1[tx]  = sc;
        sbe1[tx] = bb1[tx] + sc * (cb1[tx] - m1[tx]);
    }
    if (tx >= 32 && tx < 44) {
        int c = tx - 32;
        float sc = g2[c] * rsqrtf(v2[c] + 1e-5f);
        ss2[c]  = sc;
        sbe2[c] = bb2[c] + sc * (cb2[c] - m2[c]);
    }
    __syncthreads();

    unsigned gid = blockIdx.x * 256u + (unsigned)tx;   // 0 .. B*90-1 (exact)
    unsigned b = gid / 90u;
    int s = (int)(gid % 90u);

    const float* xb = x + (size_t)b * 360;
    float xv[9];
    int base = 4 * s - 4;
#pragma unroll
    for (int i = 0; i < 9; i++) {
        int idx = base + i;
        xv[i] = (idx >= 0 && idx < 360) ? __ldg(xb + idx) : 0.f;
    }

    float h1v[6][3];
#pragma unroll
    for (int q = 0; q < 3; q++) {
        bool valid = (2 * s - 1 + q) >= 0;
#pragma unroll
        for (int c = 0; c < 6; c++) {
            float a = 0.f;
#pragma unroll
            for (int k = 0; k < 5; k++) a = fmaf(sw1[c * 5 + k], xv[2 * q + k], a);
            a = ss1[c] * a + sbe1[c];
            h1v[c][q] = valid ? fmaxf(a, 0.f) : 0.f;
        }
    }

    float ov[12];
#pragma unroll
    for (int c2 = 0; c2 < 12; c2++) {
        float a = 0.f;
#pragma unroll
        for (int c1 = 0; c1 < 6; c1++)
#pragma unroll
            for (int q = 0; q < 3; q++)
                a = fmaf(sw2[(c2 * 6 + c1) * 3 + q], h1v[c1][q], a);
        a = ss2[c2] * a + sbe2[c2];
        ov[c2] = fmaxf(a, 0.f);
    }
    float4* o4 = reinterpret_cast<float4*>(g_xsp + (size_t)b * 1080 + s * 12);
    o4[0] = make_float4(ov[0], ov[1], ov[2],  ov[3]);
    o4[1] = make_float4(ov[4], ov[5], ov[6],  ov[7]);
    o4[2] = make_float4(ov[8], ov[9], ov[10], ov[11]);
}

// ---------------------------------------------------------------------------
// Kernel B: double LIF, 8 lanes per sample (lane owns k = lane+8i).
// Emits per-(b,t) 33-bit spike mask as uint64.
// ---------------------------------------------------------------------------
__global__ __launch_bounds__(256) void lif_kernel()
{
    unsigned gtid = blockIdx.x * 256u + threadIdx.x;   // B*8 threads
    unsigned b = gtid >> 3;
    int lane = threadIdx.x & 7;
    const float* fl = g_xsp + (size_t)b * 1080;

    float mem1[5], mem2[5];
#pragma unroll
    for (int i = 0; i < 5; i++) { mem1[i] = 0.f; mem2[i] = 0.f; }

#pragma unroll 1
    for (int t = 0; t < TSTEPS; t++) {
        const float* xt = fl + t * F;
        unsigned long long pm = 0ull;
#pragma unroll
        for (int i = 0; i < 5; i++) {
            if (i < 4 || lane == 0) {           // k = lane + 8i < 33
                int k = lane + 8 * i;
                float in = __ldg(xt + k);
                float a = 0.95f * mem1[i] + in;
                float s1 = (a > 0.5f) ? 1.f : 0.f;
                mem1[i] = a * (1.f - s1);
                float bm = 0.9f * mem2[i] + s1;
                if (bm > 0.6f) { pm |= (1ull << k); mem2[i] = 0.f; }
                else mem2[i] = bm;
            }
        }
        pm |= __shfl_xor_sync(0xffffffffu, pm, 1, 8);
        pm |= __shfl_xor_sync(0xffffffffu, pm, 2, 8);
        pm |= __shfl_xor_sync(0xffffffffu, pm, 4, 8);
        if (lane == 0) g_mask[(size_t)b * TSTEPS + t] = pm;
    }
}

// ---------------------------------------------------------------------------
// Kernel C: LSTM (FFMA2 packed gates) + head. 8 lanes x 4 samples per thread.
// Gates packed: aIF = (i,f), aGO = (g,o). One LDS.128 = 2 FFMA2 operands.
// ---------------------------------------------------------------------------
__device__ __forceinline__ float sigf(float x) {
    return __fdividef(1.f, 1.f + __expf(-x));
}
__device__ __forceinline__ float tanhfast(float x) {
    float e = __expf(2.f * x);
    return 1.f - __fdividef(2.f, e + 1.f);   // correct limits at +/-inf
}

#define NS 4   // samples per thread

__global__ __launch_bounds__(256) void lstm_head_kernel(
    const float* __restrict__ wih, const float* __restrict__ whh,
    const float* __restrict__ bih, const float* __restrict__ bhh,
    const float* __restrict__ rtw1, const float* __restrict__ rtb1,
    const float* __restrict__ rtw2, const float* __restrict__ rtb2,
    const float* __restrict__ fw,  const float* __restrict__ fb,
    const float* __restrict__ cw1, const float* __restrict__ cb1_,
    const float* __restrict__ cw2, const float* __restrict__ cb2_,
    float* __restrict__ out)
{
    __shared__ ulonglong2 sWp[F * 24];   // {(Wi,Wf),(Wg,Wo)}[k][j]
    __shared__ ulonglong2 sHp[24 * 24];
    __shared__ ulonglong2 sBs[24];
    __shared__ float s_rtw1[12 * 36], s_rtb1[12], s_rtw2[24], s_rtb2[2];
    __shared__ float s_fw[24 * 36], s_fb[24];
    __shared__ float s_cw1[12 * 24], s_cb1[12], s_cw2[60], s_cb2[5];

    int tx = threadIdx.x;
    for (int i = tx; i < F * 24; i += 256) {
        int k = i / 24, j = i % 24;
        sWp[i].x = pack2(wih[j * F + k],        wih[(24 + j) * F + k]);
        sWp[i].y = pack2(wih[(48 + j) * F + k], wih[(72 + j) * F + k]);
    }
    for (int i = tx; i < 24 * 24; i += 256) {
        int k = i / 24, j = i % 24;
        sHp[i].x = pack2(whh[j * 24 + k],        whh[(24 + j) * 24 + k]);
        sHp[i].y = pack2(whh[(48 + j) * 24 + k], whh[(72 + j) * 24 + k]);
    }
    if (tx < 24) {
        sBs[tx].x = pack2(bih[tx] + bhh[tx],           bih[24 + tx] + bhh[24 + tx]);
        sBs[tx].y = pack2(bih[48 + tx] + bhh[48 + tx], bih[72 + tx] + bhh[72 + tx]);
    }
    for (int i = tx; i < 432; i += 256) s_rtw1[i] = rtw1[i];
    if (tx < 12) s_rtb1[tx] = rtb1[tx];
    if (tx < 24) s_rtw2[tx] = rtw2[tx];
    if (tx < 2)  s_rtb2[tx] = rtb2[tx];
    for (int i = tx; i < 864; i += 256) s_fw[i] = fw[i];
    if (tx < 24) s_fb[tx] = fb[tx];
    for (int i = tx; i < 288; i += 256) s_cw1[i] = cw1[i];
    if (tx < 12) s_cb1[tx] = cb1_[tx];
    if (tx < 60) s_cw2[tx] = cw2[tx];
    if (tx < 5)  s_cb2[tx] = cb2_[tx];
    __syncthreads();

    unsigned gtid = blockIdx.x * 256u + (unsigned)tx;
    unsigned grp = gtid >> 3;          // 8 lanes per group of NS samples
    int lane = tx & 7;
    int j0 = lane * 3;
    unsigned bb = grp * NS;

    float hs[NS][3], cs[NS][3];
#pragma unroll
    for (int s = 0; s < NS; s++)
#pragma unroll
        for (int u = 0; u < 3; u++) { hs[s][u] = 0.f; cs[s][u] = 0.f; }

#pragma unroll 1
    for (int t = 0; t < TSTEPS; t++) {
        unsigned long long mk[NS];
#pragma unroll
        for (int s = 0; s < NS; s++)
            mk[s] = __ldg(&g_mask[(size_t)(bb + s) * TSTEPS + t]);

        unsigned long long aIF[NS][3], aGO[NS][3];
        {
            ulonglong2 b0 = sBs[j0], b1 = sBs[j0 + 1], b2 = sBs[j0 + 2];
#pragma unroll
            for (int s = 0; s < NS; s++) {
                aIF[s][0] = b0.x; aGO[s][0] = b0.y;
                aIF[s][1] = b1.x; aGO[s][1] = b1.y;
                aIF[s][2] = b2.x; aGO[s][2] = b2.y;
            }
        }
#pragma unroll
        for (int k = 0; k < F; k++) {
            ulonglong2 w0 = sWp[k * 24 + j0];
            ulonglong2 w1 = sWp[k * 24 + j0 + 1];
            ulonglong2 w2 = sWp[k * 24 + j0 + 2];
#pragma unroll
            for (int s = 0; s < NS; s++) {
                float f = (float)((unsigned)(mk[s] >> k) & 1u);
                unsigned long long fp = pack2(f, f);
                fma2(aIF[s][0], fp, w0.x); fma2(aGO[s][0], fp, w0.y);
                fma2(aIF[s][1], fp, w1.x); fma2(aGO[s][1], fp, w1.y);
                fma2(aIF[s][2], fp, w2.x); fma2(aGO[s][2], fp, w2.y);
            }
        }
#pragma unroll
        for (int k = 0; k < H; k++) {
            ulonglong2 w0 = sHp[k * 24 + j0];
            ulonglong2 w1 = sHp[k * 24 + j0 + 1];
            ulonglong2 w2 = sHp[k * 24 + j0 + 2];
#pragma unroll
            for (int s = 0; s < NS; s++) {
                float hk = hs[s][k % 3];
                float f = __shfl_sync(0xffffffffu, hk, k / 3, 8);
                unsigned long long fp = pack2(f, f);
                fma2(aIF[s][0], fp, w0.x); fma2(aGO[s][0], fp, w0.y);
                fma2(aIF[s][1], fp, w1.x); fma2(aGO[s][1], fp, w1.y);
                fma2(aIF[s][2], fp, w2.x); fma2(aGO[s][2], fp, w2.y);
            }
        }
#pragma unroll
        for (int s = 0; s < NS; s++) {
#pragma unroll
            for (int u = 0; u < 3; u++) {
                float2 gif = unpack2(aIF[s][u]);
                float2 ggo = unpack2(aGO[s][u]);
                float gi = sigf(gif.x);
                float gf = sigf(gif.y);
                float gg = tanhfast(ggo.x);
                float go = sigf(ggo.y);
                cs[s][u] = gf * cs[s][u] + gi * gg;
                hs[s][u] = go * tanhfast(cs[s][u]);
            }
        }
    }

    // --- head, one sample at a time (registers reused) ---
#pragma unroll 1
    for (int smp = 0; smp < NS; smp++) {
        unsigned b = bb + smp;
        const float* fl = g_xsp + (size_t)b * 1080;

        float comb[36];
#pragma unroll
        for (int k = 0; k < 24; k++) {
            float hk = hs[smp][k % 3];
            comb[k] = __shfl_sync(0xffffffffu, hk, k / 3, 8);
        }

        float pv[12];
#pragma unroll
        for (int i = 0; i < 12; i++) pv[i] = 0.f;
        const float4* x4 = reinterpret_cast<const float4*>(fl);
#pragma unroll 1
        for (int s = lane; s < 90; s += 8) {
            float4 q0 = __ldg(x4 + s * 3);
            float4 q1 = __ldg(x4 + s * 3 + 1);
            float4 q2 = __ldg(x4 + s * 3 + 2);
            pv[0] += q0.x; pv[1] += q0.y; pv[2]  += q0.z; pv[3]  += q0.w;
            pv[4] += q1.x; pv[5] += q1.y; pv[6]  += q1.z; pv[7]  += q1.w;
            pv[8] += q2.x; pv[9] += q2.y; pv[10] += q2.z; pv[11] += q2.w;
        }
#pragma unroll
        for (int i = 0; i < 12; i++) {
            float v = pv[i];
            v += __shfl_xor_sync(0xffffffffu, v, 1, 8);
            v += __shfl_xor_sync(0xffffffffu, v, 2, 8);
            v += __shfl_xor_sync(0xffffffffu, v, 4, 8);
            comb[24 + i] = v * (1.f / 90.f);
        }

        float z1[12];
#pragma unroll
        for (int i = 0; i < 12; i++) {
            float a = s_rtb1[i];
#pragma unroll
            for (int k = 0; k < 36; k++) a = fmaf(s_rtw1[i * 36 + k], comb[k], a);
            z1[i] = fmaxf(a, 0.f);
        }
        float z2[2];
#pragma unroll
        for (int i = 0; i < 2; i++) {
            float a = s_rtb2[i];
#pragma unroll
            for (int k = 0; k < 12; k++) a = fmaf(s_rtw2[i * 12 + k], z1[k], a);
            z2[i] = a;
        }
        float mx = fmaxf(z2[0], z2[1]);
        float e0 = __expf(z2[0] - mx), e1 = __expf(z2[1] - mx);
        float inv = 1.f / (e0 + e1);
        float rw0 = 0.7f * (e0 * inv), rw1 = 0.3f * (e1 * inv);
        float alpha = rw0 / (rw0 + rw1);
        float om = 1.f - alpha;

        float fin[36];
#pragma unroll
        for (int j = 0; j < 24; j++) fin[j] = comb[j] * alpha;
#pragma unroll
        for (int i = 0; i < 12; i++) fin[24 + i] = comb[24 + i] * om;

        float fused[24];
#pragma unroll
        for (int i = 0; i < 24; i++) {
            float a = s_fb[i];
#pragma unroll
            for (int k = 0; k < 36; k++) a = fmaf(s_fw[i * 36 + k], fin[k], a);
            fused[i] = fmaxf(a, 0.f);
        }
        float y1[12];
#pragma unroll
        for (int i = 0; i < 12; i++) {
            float a = s_cb1[i];
#pragma unroll
            for (int k = 0; k < 24; k++) a = fmaf(s_cw1[i * 24 + k], fused[k], a);
            y1[i] = fmaxf(a, 0.f);
        }
        if (lane == 0) {
            float* ob = out + (size_t)b * 5;
#pragma unroll
            for (int i = 0; i < 5; i++) {
                float a = s_cb2[i];
#pragma unroll
                for (int k = 0; k < 12; k++) a = fmaf(s_cw2[i * 12 + k], y1[k], a);
                ob[i] = a;
            }
        }
    }
}

extern "C" void kernel_launch(void* const* d_in, const int* in_sizes, int n_in,
                              void* d_out, int out_size) {
    const float* x   = (const float*)d_in[0];
    const float* c1w = (const float*)d_in[1];
    const float* c1b = (const float*)d_in[2];
    const float* b1g = (const float*)d_in[3];
    const float* b1b = (const float*)d_in[4];
    const float* b1m = (const float*)d_in[5];
    const float* b1v = (const float*)d_in[6];
    const float* c2w = (const float*)d_in[7];
    const float* c2b = (const float*)d_in[8];
    const float* b2g = (const float*)d_in[9];
    const float* b2b = (const float*)d_in[10];
    const float* b2m = (const float*)d_in[11];
    const float* b2v = (const float*)d_in[12];
    const float* wih = (const float*)d_in[13];
    const float* whh = (const float*)d_in[14];
    const float* bih = (const float*)d_in[15];
    const float* bhh = (const float*)d_in[16];
    const float* rtw1 = (const float*)d_in[17];
    const float* rtb1 = (const float*)d_in[18];
    const float* rtw2 = (const float*)d_in[19];
    const float* rtb2 = (const float*)d_in[20];
    const float* fw  = (const float*)d_in[21];
    const float* fb  = (const float*)d_in[22];
    const float* cw1 = (const float*)d_in[23];
    const float* cb1 = (const float*)d_in[24];
    const float* cw2 = (const float*)d_in[25];
    const float* cb2 = (const float*)d_in[26];
    float* out = (float*)d_out;

    // B*90 = 5,898,240 threads -> exactly 23040 blocks of 256
    conv_kernel<<<23040, 256>>>(x, c1w, c1b, b1g, b1b, b1m, b1v,
                                c2w, c2b, b2g, b2b, b2m, b2v);
    // B*8 threads -> 2048 blocks of 256
    lif_kernel<<<2048, 256>>>();
    // (B/4) groups * 8 lanes = 131072 threads -> 512 blocks of 256
    lstm_head_kernel<<<512, 256>>>(wih, whh, bih, bhh,
                                   rtw1, rtb1, rtw2, rtb2,
                                   fw, fb, cw1, cb1, cw2, cb2, out);
}